// round 1
// baseline (speedup 1.0000x reference)
#include <cuda_runtime.h>

#define NTPTS 144
#define NSER  24

// ---------- FMA-only fast log2 (no MUFU) ----------
// Reduction: m in [2/3, 4/3), f = m-1 in [-1/3, 1/3]; ln(1+f) Taylor (12 terms).
__device__ __forceinline__ float fast_log2f(float x) {
    int xi = __float_as_int(x);
    int e  = (xi - 0x3f2aaaab) & 0xff800000;       // 0x3f2aaaab ~ bits(2/3)
    float m  = __int_as_float(xi - e);             // [2/3, 4/3)
    float ei = (float)(e >> 23);
    float f  = m - 1.0f;                           // [-1/3, 1/3]
    // q(f) = sum_{k=0}^{11} (-1)^k f^k/(k+1);  ln(1+f) = f*q(f)
    float q = -1.0f / 12.0f;
    q = fmaf(q, f,  1.0f / 11.0f);
    q = fmaf(q, f, -0.1f);
    q = fmaf(q, f,  1.0f / 9.0f);
    q = fmaf(q, f, -0.125f);
    q = fmaf(q, f,  1.0f / 7.0f);
    q = fmaf(q, f, -1.0f / 6.0f);
    q = fmaf(q, f,  0.2f);
    q = fmaf(q, f, -0.25f);
    q = fmaf(q, f,  1.0f / 3.0f);
    q = fmaf(q, f, -0.5f);
    q = fmaf(q, f,  1.0f);
    return fmaf(f * q, 1.4426950408889634f, ei);
}

// ---------- FMA-only fast exp2 (no MUFU) ----------
// Magic-number round-to-nearest; e^g Taylor (7 terms), |g| <= 0.347.
__device__ __forceinline__ float fast_exp2f(float y) {
    y = fmaxf(y, -120.0f);                         // flush-to-tiny guard
    float fj = y + 12582912.0f;                    // 1.5 * 2^23
    int   ik = __float_as_int(fj) - 0x4b400000;    // round(y) as int
    float k  = fj - 12582912.0f;
    float f  = y - k;                              // [-0.5, 0.5]
    float g  = f * 0.6931471805599453f;
    float p = 1.0f / 720.0f;
    p = fmaf(p, g, 1.0f / 120.0f);
    p = fmaf(p, g, 1.0f / 24.0f);
    p = fmaf(p, g, 1.0f / 6.0f);
    p = fmaf(p, g, 0.5f);
    p = fmaf(p, g, 1.0f);
    p = fmaf(p, g, 1.0f);
    return __int_as_float(__float_as_int(p) + (ik << 23));
}

__global__ void __launch_bounds__(256)
dynangio_kernel(const float4* __restrict__ xv4,
                const float* __restrict__ tbuf,
                const float* __restrict__ abuf,
                const float* __restrict__ rbuf,
                float* __restrict__ out, int nrows)
{
    __shared__ float sh_t[NTPTS];
    __shared__ float sh_re[NTPTS];
    int tid = threadIdx.x;
    if (tid < NTPTS) {
        sh_t[tid]  = tbuf[tid];
        sh_re[tid] = rbuf[tid] * sinf(abuf[tid] * 0.017453292519943295f);
    }
    __syncthreads();

    int row = blockIdx.x * 8 + (tid >> 5);   // one warp per row
    if (row >= nrows) return;
    int lane = tid & 31;

    float4 xv = xv4[row];
    float dt  = xv.x;
    float s   = xv.y;
    float pp  = xv.z;
    float amp = xv.w;

    const float INV_T1B = 0.60606060606060606f;    // 1/1.65
    const float L2E     = 1.4426950408889634f;

    float a      = fmaf(pp, s, 1.0f);              // a in [1,2)
    float sprime = s + INV_T1B;
    float lg     = lgammaf(a + 1.0f);              // ln Gamma(a+1)
    float SF = 2.0f * __expf(-dt * INV_T1B) * __powf(__fdividef(s, sprime), a);
    float K  = amp * SF;
    float c0 = -lg * L2E;                          // fold 1/Gamma(a+1) into exp2 arg
    float W  = sprime * 1.8f;                      // sprime * TAU

    // rho[n] = 1 / prod_{k=1}^{n} (a+k)  — lives in registers (unrolled indices)
    float rho[NSER + 1];
    rho[0] = 1.0f;
    float an = a;
#pragma unroll
    for (int n = 1; n <= NSER; n++) { an += 1.0f; rho[n] = __fdividef(rho[n - 1], an); }

    size_t base = (size_t)row * NTPTS;
#pragma unroll
    for (int chunk = 0; chunk < 5; chunk++) {
        int j = chunk * 32 + lane;
        if (j < NTPTS) {
            float td = sh_t[j] - dt;
            float x1 = sprime * td;                 // always > 0.48
            float x2 = x1 - W;                      // may be <= 0 -> P2 = 0

            float P1;
            {
                float y    = fmaf(a, fast_log2f(x1), fmaf(-L2E, x1, c0));
                float pref = fast_exp2f(y);         // x1^a e^{-x1} / Gamma(a+1)
                float S = rho[NSER];
#pragma unroll
                for (int n = NSER - 1; n >= 0; n--) S = fmaf(S, x1, rho[n]);
                P1 = pref * S;
            }
            float P2 = 0.0f;
            if (x2 > 0.0f) {
                float y    = fmaf(a, fast_log2f(x2), fmaf(-L2E, x2, c0));
                float pref = fast_exp2f(y);
                float S = rho[NSER];
#pragma unroll
                for (int n = NSER - 1; n >= 0; n--) S = fmaf(S, x2, rho[n]);
                P2 = pref * S;
            }
            out[base + j] = K * sh_re[j] * (P1 - P2);
        }
    }
}

extern "C" void kernel_launch(void* const* d_in, const int* in_sizes, int n_in,
                              void* d_out, int out_size) {
    const float4* x  = (const float4*)d_in[0];   // (B,4) float32
    const float*  t  = (const float*)d_in[1];    // (144,)
    const float*  al = (const float*)d_in[2];    // (144,)
    const float*  R  = (const float*)d_in[3];    // (144,)
    float* out = (float*)d_out;                  // (B,144) float32
    int nrows  = in_sizes[0] / 4;
    int blocks = (nrows + 7) / 8;                // 8 warps/block, warp-per-row
    dynangio_kernel<<<blocks, 256>>>(x, t, al, R, out, nrows);
}

// round 3
// speedup vs baseline: 1.7037x; 1.7037x over previous
#include <cuda_runtime.h>

#define NTPTS 144
#define L2E 1.4426950408889634f

static __device__ __forceinline__ float mlg2(float x) {
    float r; asm("lg2.approx.f32 %0, %1;" : "=f"(r) : "f"(x)); return r;
}
static __device__ __forceinline__ float mex2(float x) {
    float r; asm("ex2.approx.f32 %0, %1;" : "=f"(r) : "f"(x)); return r;
}

// Regularized lower incomplete gamma via confluent series with per-row
// precomputed coefficients rho[n] = 1/prod_{k=1..n}(a+k):
//   P(a,x) = x^a e^{-x} / Gamma(a+1) * sum_n rho[n] x^n
// Prefactor folded into one MUFU.EX2: exp2(a*lg2(x) - x*log2e - lgamma(a+1)*log2e)
template <int NR>
struct Ser {
    float rho[NR + 1];
    __device__ __forceinline__ void init(float a) {
        rho[0] = 1.0f;
        float an = a;
#pragma unroll
        for (int n = 1; n <= NR; n++) { an += 1.0f; rho[n] = __fdividef(rho[n - 1], an); }
    }
    template <int N>
    __device__ __forceinline__ float eval(float x, float a, float c0) const {
        static_assert(N <= NR, "series length");
        float y = fmaf(a, mlg2(x), fmaf(-L2E, x, c0));
        float S = rho[N];
#pragma unroll
        for (int n = N - 1; n >= 0; n--) S = fmaf(S, x, rho[n]);
        return mex2(y) * S;
    }
};

// One warp processes one row; N1/N2 are warp-uniform series lengths for the
// P(a,x1) and P(a,x2) evaluations, chosen per row from x-range (no divergence).
template <int N1, int N2>
__device__ __forceinline__ void row_loop(int lane, float a, float c0, float sprime,
                                         float srdt, float W, float K,
                                         const float* __restrict__ sh_t,
                                         const float* __restrict__ sh_re,
                                         float* __restrict__ outp)
{
    Ser<N1> ser;
    ser.init(a);
#pragma unroll
    for (int chunk = 0; chunk < 5; chunk++) {
        int j = chunk * 32 + lane;
        if (j < NTPTS) {
            float x1 = fmaf(sprime, sh_t[j], -srdt);
            float x2 = x1 - W;
            float P = ser.template eval<N1>(x1, a, c0);
            if (x2 > 0.0f) P -= ser.template eval<N2>(x2, a, c0);
            outp[j] = K * sh_re[j] * P;
        }
    }
}

__device__ __forceinline__ int tier_of(float xmax) {
    return (xmax <= 2.75f) ? 0 : ((xmax <= 4.5f) ? 1 : 2);
}

__global__ void __launch_bounds__(256)
dynangio_kernel(const float4* __restrict__ xv4,
                const float* __restrict__ tbuf,
                const float* __restrict__ abuf,
                const float* __restrict__ rbuf,
                float* __restrict__ out, int nrows)
{
    __shared__ float sh_t[NTPTS];
    __shared__ float sh_re[NTPTS];
    int tid = threadIdx.x;
    if (tid < NTPTS) {
        sh_t[tid]  = tbuf[tid];
        sh_re[tid] = rbuf[tid] * sinf(abuf[tid] * 0.017453292519943295f);
    }
    __syncthreads();

    int row = blockIdx.x * 8 + (tid >> 5);
    if (row >= nrows) return;
    int lane = tid & 31;

    float4 xv = xv4[row];
    float dt  = xv.x;
    float s   = xv.y;
    float pp  = xv.z;
    float amp = xv.w;

    const float INV_T1B = 0.60606060606060606f;   // 1/1.65

    float a      = fmaf(pp, s, 1.0f);             // a in [1,2)
    float sprime = s + INV_T1B;
    float c0     = -lgammaf(a + 1.0f) * L2E;      // fold 1/Gamma(a+1) into exp2
    // SF = 2 exp(-dt/T1B) (s/s')^a  via MUFU
    float SF = 2.0f * mex2(fmaf(-dt * INV_T1B, L2E,
                                a * (mlg2(s) - mlg2(sprime))));
    float K    = amp * SF;
    float W    = sprime * 1.8f;                   // s' * TAU
    float srdt = sprime * dt;

    float tmax  = sh_t[NTPTS - 1];
    float x1max = fmaf(sprime, tmax, -srdt);
    float x2max = x1max - W;
    int t1 = tier_of(x1max);
    int t2 = tier_of(x2max);                      // always <= t1

    float* outp = out + (size_t)row * NTPTS;

    switch (t1 * 3 + t2) {
        case 0: row_loop<10, 10>(lane, a, c0, sprime, srdt, W, K, sh_t, sh_re, outp); break;
        case 3: row_loop<14, 10>(lane, a, c0, sprime, srdt, W, K, sh_t, sh_re, outp); break;
        case 4: row_loop<14, 14>(lane, a, c0, sprime, srdt, W, K, sh_t, sh_re, outp); break;
        case 6: row_loop<19, 10>(lane, a, c0, sprime, srdt, W, K, sh_t, sh_re, outp); break;
        case 7: row_loop<19, 14>(lane, a, c0, sprime, srdt, W, K, sh_t, sh_re, outp); break;
        default: row_loop<19, 19>(lane, a, c0, sprime, srdt, W, K, sh_t, sh_re, outp); break;
    }
}

extern "C" void kernel_launch(void* const* d_in, const int* in_sizes, int n_in,
                              void* d_out, int out_size) {
    const float4* x  = (const float4*)d_in[0];   // (B,4) float32
    const float*  t  = (const float*)d_in[1];    // (144,)
    const float*  al = (const float*)d_in[2];    // (144,)
    const float*  R  = (const float*)d_in[3];    // (144,)
    float* out = (float*)d_out;                  // (B,144) float32
    int nrows  = in_sizes[0] / 4;
    int blocks = (nrows + 7) / 8;                // 8 warps/block, warp-per-row
    dynangio_kernel<<<blocks, 256>>>(x, t, al, R, out, nrows);
}

// round 4
// speedup vs baseline: 1.8503x; 1.0860x over previous
#include <cuda_runtime.h>

#define NTPTS 144
#define L2E 1.4426950408889634f
typedef unsigned long long u64;

static __device__ __forceinline__ float mlg2(float x){ float r; asm("lg2.approx.f32 %0, %1;":"=f"(r):"f"(x)); return r; }
static __device__ __forceinline__ float mex2(float x){ float r; asm("ex2.approx.f32 %0, %1;":"=f"(r):"f"(x)); return r; }
static __device__ __forceinline__ u64 pk2(float lo, float hi){ u64 r; asm("mov.b64 %0, {%1,%2};":"=l"(r):"f"(lo),"f"(hi)); return r; }
static __device__ __forceinline__ void upk2(float& lo, float& hi, u64 v){ asm("mov.b64 {%0,%1}, %2;":"=f"(lo),"=f"(hi):"l"(v)); }
static __device__ __forceinline__ u64 ffma2(u64 a, u64 b, u64 c){ u64 d; asm("fma.rn.f32x2 %0, %1, %2, %3;":"=l"(d):"l"(a),"l"(b),"l"(c)); return d; }

// One warp per row. Packed evaluation: lane pair {x1, x2} runs one shared
// Horner (rho identical), prefactors exp2(a*lg2(x) - L2E*x + c0) with K folded
// into c0. x2<=0 half produces NaN/garbage and is predicated out.
template <int N>
__device__ __forceinline__ void row_loop(int lane, float a, u64 a2, u64 c02,
                                         u64 nL2E2, u64 sp2, u64 off2,
                                         const u64* __restrict__ sh_t2,
                                         const float* __restrict__ sh_re,
                                         float* __restrict__ outp)
{
    u64 rp[N + 1];                       // rho[n] = 1/prod(a+k), duplicated
    rp[0] = pk2(1.0f, 1.0f);
    float r = 1.0f, an = a;
#pragma unroll
    for (int n = 1; n <= N; n++) { an += 1.0f; r = __fdividef(r, an); rp[n] = pk2(r, r); }

#pragma unroll
    for (int chunk = 0; chunk < 5; chunk++) {
        int j = chunk * 32 + lane;
        if (chunk < 4 || lane < NTPTS - 128) {
            u64 xp = ffma2(sp2, sh_t2[j], off2);          // {x1, x2}
            u64 S = rp[N];
#pragma unroll
            for (int n = N - 1; n >= 0; n--) S = ffma2(S, xp, rp[n]);
            float x1, x2; upk2(x1, x2, xp);
            u64 lgp = pk2(mlg2(x1), mlg2(x2));
            u64 yp = ffma2(a2, lgp, ffma2(nL2E2, xp, c02));
            float y1, y2; upk2(y1, y2, yp);
            float S1, S2; upk2(S1, S2, S);
            float P1 = mex2(y1) * S1;
            float P2 = (x2 > 0.0f) ? mex2(y2) * S2 : 0.0f;
            outp[j] = sh_re[j] * (P1 - P2);
        }
    }
}

__global__ void __launch_bounds__(256)
dynangio_kernel(const float4* __restrict__ xv4,
                const float* __restrict__ tbuf,
                const float* __restrict__ abuf,
                const float* __restrict__ rbuf,
                float* __restrict__ out, int nrows)
{
    __shared__ u64   sh_t2[NTPTS];       // {t, t} duplicated for packed fma
    __shared__ float sh_re[NTPTS];
    int tid = threadIdx.x;
    if (tid < NTPTS) {
        float tv = tbuf[tid];
        sh_t2[tid] = pk2(tv, tv);
        sh_re[tid] = rbuf[tid] * sinf(abuf[tid] * 0.017453292519943295f);
    }
    __syncthreads();

    int row = blockIdx.x * 8 + (tid >> 5);
    if (row >= nrows) return;
    int lane = tid & 31;

    float4 xv = xv4[row];
    float dt  = xv.x;
    float s   = xv.y;
    float pp  = xv.z;
    float amp = xv.w;

    const float INV_T1B = 0.60606060606060606f;    // 1/1.65

    float a      = fmaf(pp, s, 1.0f);              // a in [1,2)
    float sprime = s + INV_T1B;
    float srdt   = sprime * dt;
    float W      = sprime * 1.8f;                  // s' * TAU
    // c0 = lg2( amp * 2 * exp(-dt/T1B) * (s/s')^a / Gamma(a+1) )
    float c0 = 1.0f
             - dt * INV_T1B * L2E
             + a * (mlg2(s) - mlg2(sprime))
             + mlg2(amp)
             - lgammaf(a + 1.0f) * L2E;

    u64 a2    = pk2(a, a);
    u64 c02   = pk2(c0, c0);
    u64 nL2E2 = pk2(-L2E, -L2E);
    u64 sp2   = pk2(sprime, sprime);
    u64 off2  = pk2(-srdt, -srdt - W);

    // Warp-uniform series length from per-row max argument (lanes share a row)
    float thi, tlo; upk2(tlo, thi, sh_t2[NTPTS - 1]);
    float x1max = fmaf(sprime, thi, -srdt);

    float* outp = out + (size_t)row * NTPTS;

    if (x1max <= 2.75f)
        row_loop<10>(lane, a, a2, c02, nL2E2, sp2, off2, sh_t2, sh_re, outp);
    else if (x1max <= 4.5f)
        row_loop<14>(lane, a, a2, c02, nL2E2, sp2, off2, sh_t2, sh_re, outp);
    else
        row_loop<19>(lane, a, a2, c02, nL2E2, sp2, off2, sh_t2, sh_re, outp);
}

extern "C" void kernel_launch(void* const* d_in, const int* in_sizes, int n_in,
                              void* d_out, int out_size) {
    const float4* x  = (const float4*)d_in[0];   // (B,4) float32
    const float*  t  = (const float*)d_in[1];    // (144,)
    const float*  al = (const float*)d_in[2];    // (144,)
    const float*  R  = (const float*)d_in[3];    // (144,)
    float* out = (float*)d_out;                  // (B,144) float32
    int nrows  = in_sizes[0] / 4;
    int blocks = (nrows + 7) / 8;                // 8 warps/block, warp-per-row
    dynangio_kernel<<<blocks, 256>>>(x, t, al, R, out, nrows);
}